// round 1
// baseline (speedup 1.0000x reference)
#include <cuda_runtime.h>
#include <cstdint>

// ---------------- physical constants (match reference exactly) -------------
#define ANGSTROM_TO_METER 1e-10f
#define KQQ               8987551792.3f           // Coulomb constant
#define ECH               1.602176634e-19f        // electron charge
#define INV_EV            6.241509074460763e18f   // 1/EV_TO_JOULE
#define FSCALE            6.241509074460763e8f    // ANGSTROM_TO_METER / EV_TO_JOULE
#define BETA              18.7f
#define R0_M              (2.2f * 1e-10f)
#define EW_P              0.3275911f
#define EW_A0             0.254829592f
#define EW_A1             (-0.284496736f)
#define EW_A2             1.421413741f
#define EW_A3             (-1.453152027f)
#define EW_A4             1.061405429f
#define EW_F              2.0f

#define N_GRAPHS 256

// double-precision energy accumulator scratch (no device mallocs allowed)
__device__ double g_energy_acc[N_GRAPHS];

// -------------------- kernel 1: zero output + scratch ----------------------
__global__ void zero_kernel(float* __restrict__ out, int n_out) {
    int i = blockIdx.x * blockDim.x + threadIdx.x;
    if (i < n_out) out[i] = 0.0f;
    if (i < N_GRAPHS) g_energy_acc[i] = 0.0;
}

// -------------------- kernel 2: fused per-edge pass -------------------------
__global__ __launch_bounds__(256) void edge_kernel(
    const float* __restrict__ dij,        // [E,3] Angstrom
    const float* __restrict__ q,          // [N] charge (e)
    const float* __restrict__ g_ewald,    // [1]
    const int*   __restrict__ row,        // [E]
    const int*   __restrict__ col,        // [E]
    const int*   __restrict__ batch,      // [N] atom -> graph (0..255)
    float*       __restrict__ force,      // [N,3] output (eV/A)
    int n_edges)
{
    __shared__ float s_e[N_GRAPHS];
    s_e[threadIdx.x] = 0.0f;
    __syncthreads();

    const float g = g_ewald[0];
    const int stride = gridDim.x * blockDim.x;

    for (int i = blockIdx.x * blockDim.x + threadIdx.x; i < n_edges; i += stride) {
        // load edge geometry (Angstrom -> meters)
        float dx = dij[3 * i + 0] * ANGSTROM_TO_METER;
        float dy = dij[3 * i + 1] * ANGSTROM_TO_METER;
        float dz = dij[3 * i + 2] * ANGSTROM_TO_METER;
        int r = row[i];
        int c = col[i];

        float rij  = sqrtf(dx * dx + dy * dy + dz * dz);
        float inv_r = 1.0f / rij;

        float qr = q[r] * ECH;
        float qc = q[c] * ECH;
        float pref = KQQ * qr * qc * inv_r;

        // short-range exponential damping
        float damp = (rij < R0_M)
                       ? expf(-BETA * (R0_M - rij) * (1.0f / R0_M))
                       : 1.0f;
        float pd = pref * damp;

        // Ewald real-space correction (A&S erfc polynomial)
        float grij  = g * rij;
        float expm2 = expf(-grij * grij);
        float t     = 1.0f / (1.0f + EW_P * grij);
        float erfc  = t * (EW_A0 + t * (EW_A1 + t * (EW_A2 + t * (EW_A3 + t * EW_A4)))) * expm2;

        float ecoul = 0.5f * pd + pref * (erfc - 1.0f);
        float fcoul = (pd + pref * (erfc + EW_F * grij * expm2 - 1.0f)) * inv_r;

        // force vector in eV/Angstrom
        float s  = fcoul * inv_r * FSCALE;
        float fx = dx * s;
        float fy = dy * s;
        float fz = dz * s;

        // scatter: force[row] += f, force[col] -= f
        atomicAdd(&force[3 * r + 0],  fx);
        atomicAdd(&force[3 * r + 1],  fy);
        atomicAdd(&force[3 * r + 2],  fz);
        atomicAdd(&force[3 * c + 0], -fx);
        atomicAdd(&force[3 * c + 1], -fy);
        atomicAdd(&force[3 * c + 2], -fz);

        // energy: edge -> graph bin (batch[row]) in shared memory
        int gidx = batch[r];
        atomicAdd(&s_e[gidx], ecoul * INV_EV);
    }

    __syncthreads();
    // flush block bins to global double accumulators
    float v = s_e[threadIdx.x];
    if (v != 0.0f) atomicAdd(&g_energy_acc[threadIdx.x], (double)v);
}

// -------------------- kernel 3: write energy to output ----------------------
__global__ void finish_kernel(float* __restrict__ out_energy) {
    int i = threadIdx.x;
    if (i < N_GRAPHS) out_energy[i] = (float)g_energy_acc[i];
}

// ---------------------------------------------------------------------------
extern "C" void kernel_launch(void* const* d_in, const int* in_sizes, int n_in,
                              void* d_out, int out_size)
{
    const float* dij     = (const float*)d_in[0];   // [E,3]
    const float* q       = (const float*)d_in[1];   // [N]
    const float* g_ewald = (const float*)d_in[2];   // [1]
    const int*   row     = (const int*)d_in[3];     // [E]
    const int*   col     = (const int*)d_in[4];     // [E]
    const int*   batch   = (const int*)d_in[5];     // [N]

    int n_edges = in_sizes[0] / 3;

    float* out        = (float*)d_out;
    float* out_energy = out;                 // [256]
    float* out_force  = out + N_GRAPHS;      // [N,3]

    // zero output + scratch
    {
        int threads = 256;
        int blocks = (out_size + threads - 1) / threads;
        zero_kernel<<<blocks, threads>>>(out, out_size);
    }

    // main fused pass
    {
        int threads = 256;
        int blocks = 148 * 16;  // grid-stride, ~13 edges/thread
        edge_kernel<<<blocks, threads>>>(dij, q, g_ewald, row, col, batch,
                                         out_force, n_edges);
    }

    // energy to output
    finish_kernel<<<1, N_GRAPHS>>>(out_energy);
}

// round 2
// speedup vs baseline: 2.0107x; 2.0107x over previous
#include <cuda_runtime.h>
#include <cstdint>

// ---------------- constants (eV / Angstrom natural units) -------------------
// pref_eV = KQQ * e^2 / 1e-10 / e = 14.399645478425668 eV*A
#define CE        14.399645478425668f
#define BETA_OVR0 8.5f            // 18.7 / 2.2
#define BETA      18.7f
#define R0_A      2.2f
#define EW_P      0.3275911f
#define EW_A0     0.254829592f
#define EW_A1     (-0.284496736f)
#define EW_A2     1.421413741f
#define EW_A3     (-1.453152027f)
#define EW_A4     1.061405429f
#define EW_F      2.0f
#define A2M       1e-10f          // Angstrom -> meter (for g_ewald scaling)

#define N_ATOMS_MAX 200000
#define N_GRAPHS    256

// scratch: per-atom accumulator {fx, fy, fz, e_atom}  (3.2 MB, L2-resident)
__device__ float4 g_f4[N_ATOMS_MAX];
// per-graph energy accumulators (double for order-insensitive accuracy)
__device__ double g_eacc[N_GRAPHS];

// -------------------- kernel 1: zero scratch --------------------------------
__global__ void zero_kernel(int n4) {
    int i = blockIdx.x * blockDim.x + threadIdx.x;
    if (i < n4) ((float*)g_f4)[i] = 0.0f;
    if (i < N_GRAPHS) g_eacc[i] = 0.0;
}

// -------------------- kernel 2: fused per-edge pass --------------------------
__global__ __launch_bounds__(256) void edge_kernel(
    const float* __restrict__ dij,        // [E,3] Angstrom
    const float* __restrict__ q,          // [N] charge (e)
    const float* __restrict__ g_ewald,    // [1] 1/m
    const int*   __restrict__ row,        // [E]
    const int*   __restrict__ col,        // [E]
    int n_edges)
{
    const float gA = g_ewald[0] * A2M;    // 1/Angstrom
    const int stride = gridDim.x * blockDim.x;

    for (int i = blockIdx.x * blockDim.x + threadIdx.x; i < n_edges; i += stride) {
        float dx = dij[3 * i + 0];
        float dy = dij[3 * i + 1];
        float dz = dij[3 * i + 2];
        int r = row[i];
        int c = col[i];

        float r2    = fmaf(dx, dx, fmaf(dy, dy, dz * dz));
        float inv_r = rsqrtf(r2);
        float rij   = r2 * inv_r;                       // Angstrom

        float pref = CE * q[r] * q[c] * inv_r;          // eV

        // short-range exponential damping (rij < 2.2 A)
        float damp = (rij < R0_A)
                       ? __expf(fmaf(BETA_OVR0, rij, -BETA))
                       : 1.0f;

        // Ewald real-space correction (A&S erfc polynomial)
        float grij  = gA * rij;
        float expm2 = __expf(-grij * grij);
        float t     = 1.0f / fmaf(EW_P, grij, 1.0f);
        float erfc  = t * fmaf(t, fmaf(t, fmaf(t, fmaf(t, EW_A4, EW_A3), EW_A2), EW_A1), EW_A0) * expm2;

        float ecoul = pref * (fmaf(0.5f, damp, erfc) - 1.0f);                    // eV
        float fcoul = pref * (damp + erfc + EW_F * grij * expm2 - 1.0f) * inv_r; // eV/A

        // force vector in eV/A: (dij/rij) * fcoul
        float s  = fcoul * inv_r;
        float fx = dx * s;
        float fy = dy * s;
        float fz = dz * s;

        // one 128-bit vector atomic per endpoint; energy packed in .w of row side
        atomicAdd(&g_f4[r], make_float4( fx,  fy,  fz, ecoul));
        atomicAdd(&g_f4[c], make_float4(-fx, -fy, -fz, 0.0f));
    }
}

// -------------------- kernel 3: unpack force + bin energy --------------------
__global__ __launch_bounds__(256) void finish_kernel(
    const int* __restrict__ batch,        // [N] atom -> graph
    float*     __restrict__ out_force,    // [N,3]
    int n_atoms)
{
    __shared__ float s_e[N_GRAPHS];
    s_e[threadIdx.x] = 0.0f;
    __syncthreads();

    int a = blockIdx.x * blockDim.x + threadIdx.x;
    if (a < n_atoms) {
        float4 f = g_f4[a];
        out_force[3 * a + 0] = f.x;
        out_force[3 * a + 1] = f.y;
        out_force[3 * a + 2] = f.z;
        atomicAdd(&s_e[batch[a]], f.w);
    }
    __syncthreads();

    float v = s_e[threadIdx.x];
    if (v != 0.0f) atomicAdd(&g_eacc[threadIdx.x], (double)v);
}

// -------------------- kernel 4: energy to output -----------------------------
__global__ void energy_kernel(float* __restrict__ out_energy) {
    out_energy[threadIdx.x] = (float)g_eacc[threadIdx.x];
}

// -----------------------------------------------------------------------------
extern "C" void kernel_launch(void* const* d_in, const int* in_sizes, int n_in,
                              void* d_out, int out_size)
{
    const float* dij     = (const float*)d_in[0];   // [E,3]
    const float* q       = (const float*)d_in[1];   // [N]
    const float* g_ewald = (const float*)d_in[2];   // [1]
    const int*   row     = (const int*)d_in[3];     // [E]
    const int*   col     = (const int*)d_in[4];     // [E]
    const int*   batch   = (const int*)d_in[5];     // [N]

    int n_edges = in_sizes[0] / 3;
    int n_atoms = in_sizes[1];

    float* out        = (float*)d_out;
    float* out_energy = out;                 // [256]
    float* out_force  = out + N_GRAPHS;      // [N,3]

    // zero scratch (output force/energy fully overwritten by finish kernels)
    {
        int n4 = n_atoms * 4;
        zero_kernel<<<(n4 + 255) / 256, 256>>>(n4);
    }

    // main fused pass
    edge_kernel<<<148 * 16, 256>>>(dij, q, g_ewald, row, col, n_edges);

    // unpack + energy binning
    finish_kernel<<<(n_atoms + 255) / 256, 256>>>(batch, out_force, n_atoms);

    // energy bins to output
    energy_kernel<<<1, N_GRAPHS>>>(out_energy);
}

// round 3
// speedup vs baseline: 2.0201x; 1.0046x over previous
#include <cuda_runtime.h>
#include <cstdint>

// ---------------- constants (eV / Angstrom natural units) -------------------
#define CE        14.399645478425668f   // KQQ * e / 1e-10 (eV*A per e^2)
#define BETA_OVR0 8.5f                  // 18.7 / 2.2
#define BETA      18.7f
#define R0_A      2.2f
#define EW_P      0.3275911f
#define EW_A0     0.254829592f
#define EW_A1     (-0.284496736f)
#define EW_A2     1.421413741f
#define EW_A3     (-1.453152027f)
#define EW_A4     1.061405429f
#define EW_F      2.0f
#define A2M       1e-10f

#define N_ATOMS_MAX 200000
#define N_GRAPHS    256

// scratch: per-atom accumulator {fx, fy, fz, e_atom}  (3.2 MB, L2-resident)
__device__ float4 g_f4[N_ATOMS_MAX];

// -------------------- kernel 1: zero scratch + energy out -------------------
__global__ void zero_kernel(float* __restrict__ out_energy, int n4) {
    int i = blockIdx.x * blockDim.x + threadIdx.x;
    if (i < n4) ((float*)g_f4)[i] = 0.0f;
    if (i < N_GRAPHS) out_energy[i] = 0.0f;
}

// -------------------- per-edge math (inlined 4x) -----------------------------
__device__ __forceinline__ void do_edge(
    float dx, float dy, float dz, int r, int c,
    const float* __restrict__ q, float gA)
{
    float r2    = fmaf(dx, dx, fmaf(dy, dy, dz * dz));
    float inv_r = rsqrtf(r2);
    float rij   = r2 * inv_r;                       // Angstrom

    float pref = CE * q[r] * q[c] * inv_r;          // eV

    // short-range exponential damping (rij < 2.2 A)
    float damp = (rij < R0_A) ? __expf(fmaf(BETA_OVR0, rij, -BETA)) : 1.0f;

    // Ewald real-space correction (A&S erfc polynomial)
    float grij  = gA * rij;
    float expm2 = __expf(-grij * grij);
    float t     = 1.0f / fmaf(EW_P, grij, 1.0f);
    float erfc  = t * fmaf(t, fmaf(t, fmaf(t, fmaf(t, EW_A4, EW_A3), EW_A2), EW_A1), EW_A0) * expm2;

    float ecoul = pref * (fmaf(0.5f, damp, erfc) - 1.0f);                    // eV
    float fcoul = pref * (damp + erfc + EW_F * grij * expm2 - 1.0f) * inv_r; // eV/A

    float s  = fcoul * inv_r;
    float fx = dx * s;
    float fy = dy * s;
    float fz = dz * s;

    atomicAdd(&g_f4[r], make_float4( fx,  fy,  fz, ecoul));
    atomicAdd(&g_f4[c], make_float4(-fx, -fy, -fz, 0.0f));
}

// -------------------- kernel 2: fused per-edge pass (4 edges/iter) ----------
__global__ __launch_bounds__(256) void edge_kernel(
    const float4* __restrict__ dij4,      // [E*3/4] = [E,3] viewed as float4
    const float*  __restrict__ q,         // [N]
    const float*  __restrict__ g_ewald,   // [1] 1/m
    const int4*   __restrict__ row4,      // [E/4]
    const int4*   __restrict__ col4,      // [E/4]
    int n_chunks)                          // E/4
{
    const float gA = g_ewald[0] * A2M;    // 1/Angstrom
    const int stride = gridDim.x * blockDim.x;

    for (int j = blockIdx.x * blockDim.x + threadIdx.x; j < n_chunks; j += stride) {
        float4 d0 = dij4[3 * j + 0];
        float4 d1 = dij4[3 * j + 1];
        float4 d2 = dij4[3 * j + 2];
        int4 r = row4[j];
        int4 c = col4[j];

        do_edge(d0.x, d0.y, d0.z, r.x, c.x, q, gA);
        do_edge(d0.w, d1.x, d1.y, r.y, c.y, q, gA);
        do_edge(d1.z, d1.w, d2.x, r.z, c.z, q, gA);
        do_edge(d2.y, d2.z, d2.w, r.w, c.w, q, gA);
    }
}

// tail handler for n_edges not divisible by 4
__global__ void edge_tail_kernel(
    const float* __restrict__ dij,
    const float* __restrict__ q,
    const float* __restrict__ g_ewald,
    const int*   __restrict__ row,
    const int*   __restrict__ col,
    int e_start, int n_edges)
{
    int i = e_start + blockIdx.x * blockDim.x + threadIdx.x;
    if (i < n_edges) {
        const float gA = g_ewald[0] * A2M;
        do_edge(dij[3 * i], dij[3 * i + 1], dij[3 * i + 2], row[i], col[i], q, gA);
    }
}

// -------------------- kernel 3: unpack force + bin energy --------------------
__global__ __launch_bounds__(256) void finish_kernel(
    const int* __restrict__ batch,        // [N] atom -> graph
    float*     __restrict__ out_energy,   // [256]
    float*     __restrict__ out_force,    // [N,3]
    int n_atoms)
{
    __shared__ float s_e[N_GRAPHS];
    s_e[threadIdx.x] = 0.0f;
    __syncthreads();

    int a = blockIdx.x * blockDim.x + threadIdx.x;
    if (a < n_atoms) {
        float4 f = g_f4[a];
        out_force[3 * a + 0] = f.x;
        out_force[3 * a + 1] = f.y;
        out_force[3 * a + 2] = f.z;
        atomicAdd(&s_e[batch[a]], f.w);
    }
    __syncthreads();

    float v = s_e[threadIdx.x];
    if (v != 0.0f) atomicAdd(&out_energy[threadIdx.x], v);
}

// -----------------------------------------------------------------------------
extern "C" void kernel_launch(void* const* d_in, const int* in_sizes, int n_in,
                              void* d_out, int out_size)
{
    const float* dij     = (const float*)d_in[0];   // [E,3]
    const float* q       = (const float*)d_in[1];   // [N]
    const float* g_ewald = (const float*)d_in[2];   // [1]
    const int*   row     = (const int*)d_in[3];     // [E]
    const int*   col     = (const int*)d_in[4];     // [E]
    const int*   batch   = (const int*)d_in[5];     // [N]

    int n_edges = in_sizes[0] / 3;
    int n_atoms = in_sizes[1];

    float* out        = (float*)d_out;
    float* out_energy = out;                 // [256]
    float* out_force  = out + N_GRAPHS;      // [N,3]

    // zero scratch + energy output
    {
        int n4 = n_atoms * 4;
        zero_kernel<<<(n4 + 255) / 256, 256>>>(out_energy, n4);
    }

    // main fused pass, 4 edges per thread-iteration
    int n_chunks = n_edges / 4;
    edge_kernel<<<148 * 8, 256>>>((const float4*)dij, q, g_ewald,
                                  (const int4*)row, (const int4*)col, n_chunks);

    int tail = n_edges - n_chunks * 4;
    if (tail > 0) {
        edge_tail_kernel<<<1, 256>>>(dij, q, g_ewald, row, col,
                                     n_chunks * 4, n_edges);
    }

    // unpack + energy binning (fp32, matches reference accumulation precision)
    finish_kernel<<<(n_atoms + 255) / 256, 256>>>(batch, out_energy, out_force, n_atoms);
}